// round 5
// baseline (speedup 1.0000x reference)
#include <cuda_runtime.h>

// BackEdgeConv2d fused: out = x * !(5 <= boxcount7x7(x >= 128/255, reflect) <= 19)
// x: [16,3,1024,1024] fp32. Single barrier; register-rolling vertical sums;
// SIMD prefix-sum horizontal; PRMT (inline PTX) sign-replicate masking.

#define TILE_W 128
#define TILE_H 128
#define KPAD 3
#define PH (TILE_H + 2*KPAD)        // 134 padded rows
#define WPR 34                      // 136 cond bytes/row: byte j <-> global col c0-4+j
#define ROWB 136                    // row stride in bytes
#define NTHREADS 256

// PTX prmt: guarantees default-mode semantics incl. selector-bit-3 MSB-replicate.
__device__ __forceinline__ unsigned prmt(unsigned a, unsigned b, unsigned s) {
    unsigned r;
    asm("prmt.b32 %0, %1, %2, %3;" : "=r"(r) : "r"(a), "r"(b), "r"(s));
    return r;
}

__global__ __launch_bounds__(NTHREADS)
void backedge_kernel(const float* __restrict__ x, float* __restrict__ out,
                     int H, int W) {
    __shared__ __align__(16) unsigned int scond[PH * WPR];   // 18224 B

    const int tid = threadIdx.x;
    const int c0 = blockIdx.x * TILE_W;
    const int r0 = blockIdx.y * TILE_H;
    const long long plane = (long long)blockIdx.z * H * W;
    const float* xp = x + plane;
    float* op = out + plane;
    const float T = 128.0f / 255.0f;

    // ---- Phase 1: padded binary cond map, one uint32 word (4 px) per iter
    #pragma unroll 1
    for (int wi = tid; wi < PH * WPR; wi += NTHREADS) {
        int pr = wi / WPR;                    // const divisor -> mul.hi
        int w  = wi - pr * WPR;
        int gr = r0 + pr - KPAD;
        int gc = c0 + (w << 2) - 4;
        float4 v;
        if ((unsigned)gr < (unsigned)H && (unsigned)gc <= (unsigned)(W - 4)) {
            v = *(const float4*)(xp + gr * W + gc);          // aligned, coalesced
        } else {
            int rr = gr < 0 ? -gr : (gr >= H ? 2 * H - 2 - gr : gr);
            const float* rowp = xp + rr * W;
            int g0 = gc, g1 = gc + 1, g2 = gc + 2, g3 = gc + 3;
            g0 = g0 < 0 ? -g0 : (g0 >= W ? 2 * W - 2 - g0 : g0);
            g1 = g1 < 0 ? -g1 : (g1 >= W ? 2 * W - 2 - g1 : g1);
            g2 = g2 < 0 ? -g2 : (g2 >= W ? 2 * W - 2 - g2 : g2);
            g3 = g3 < 0 ? -g3 : (g3 >= W ? 2 * W - 2 - g3 : g3);
            v.x = rowp[g0]; v.y = rowp[g1]; v.z = rowp[g2]; v.w = rowp[g3];
        }
        unsigned int b0 = (v.x >= T) ? 1u : 0u;
        unsigned int b1 = (v.y >= T) ? (1u << 8) : 0u;
        unsigned int b2 = (v.z >= T) ? (1u << 16) : 0u;
        unsigned int b3 = (v.w >= T) ? (1u << 24) : 0u;
        scond[wi] = (b0 | b1) | (b2 | b3);
    }
    __syncthreads();

    // ---- Phase 2+3 merged: each thread owns 8 output px (byte span [8tx, 8tx+16))
    //      for a band of 8 rows. Vertical 7-sum rolls in registers (byte-SIMD).
    const int tx = tid & 15;          // -> output px 8tx .. 8tx+7
    const int ty = tid >> 4;          // 16 bands of 8 rows
    const int span = tx << 3;         // byte offset in padded row (8B aligned)
    const int r_base = ty << 3;
    const unsigned char* condb = (const unsigned char*)scond;

    unsigned v0 = 0, v1 = 0, v2 = 0, v3 = 0;     // bytes B0..B15 vertical sums
    #pragma unroll
    for (int k = 0; k < 7; k++) {
        const uint2* p = (const uint2*)(condb + (r_base + k) * ROWB + span);
        uint2 lo = p[0], hi = p[1];
        v0 += lo.x; v1 += lo.y; v2 += hi.x; v3 += hi.y;
    }

    #pragma unroll
    for (int rr = 0; rr < 8; rr++) {
        const int r = r_base + rr;

        // byte prefix sums P[0..15] across the 16-byte span (max 112 < 256)
        unsigned p0 = v0 * 0x01010101u;
        unsigned p1 = v1 * 0x01010101u + prmt(p0, 0, 0x3333);
        unsigned p2 = v2 * 0x01010101u + prmt(p1, 0, 0x3333);
        unsigned p3 = v3 * 0x01010101u + prmt(p2, 0, 0x3333);
        // h_i = P[i+7] - P[i]  (window bytes i+1..i+7), packed 4/word
        unsigned hA = __vsub4(prmt(p1, p2, 0x6543), p0);   // px 0..3
        unsigned hB = __vsub4(prmt(p2, p3, 0x6543), p1);   // px 4..7

        // band 5..19 per byte -> MSB flag (h <= 49, no cross-byte carry)
        unsigned mA = (hA + 0x7B7B7B7Bu) & ~(hA + 0x6C6C6C6Cu) & 0x80808080u;
        unsigned mB = (hB + 0x7B7B7B7Bu) & ~(hB + 0x6C6C6C6Cu) & 0x80808080u;

        const float4* gx = (const float4*)(xp + (r0 + r) * W + c0 + span);
        float4 xa = gx[0], xb = gx[1];

        // sign-replicate each mask byte to a full 32-bit lane mask (PTX prmt)
        float4 oa, ob;
        oa.x = __uint_as_float(__float_as_uint(xa.x) & ~prmt(mA, 0, 0x8888));
        oa.y = __uint_as_float(__float_as_uint(xa.y) & ~prmt(mA, 0, 0x9999));
        oa.z = __uint_as_float(__float_as_uint(xa.z) & ~prmt(mA, 0, 0xAAAA));
        oa.w = __uint_as_float(__float_as_uint(xa.w) & ~prmt(mA, 0, 0xBBBB));
        ob.x = __uint_as_float(__float_as_uint(xb.x) & ~prmt(mB, 0, 0x8888));
        ob.y = __uint_as_float(__float_as_uint(xb.y) & ~prmt(mB, 0, 0x9999));
        ob.z = __uint_as_float(__float_as_uint(xb.z) & ~prmt(mB, 0, 0xAAAA));
        ob.w = __uint_as_float(__float_as_uint(xb.w) & ~prmt(mB, 0, 0xBBBB));

        float4* go = (float4*)(op + (r0 + r) * W + c0 + span);
        __stcs(go,     oa);
        __stcs(go + 1, ob);

        // roll vertical sums: v += cond[r+7] - cond[r]  (byte-SIMD safe)
        if (rr < 7) {
            const uint2* pa = (const uint2*)(condb + (r + 7) * ROWB + span);
            const uint2* ps = (const uint2*)(condb + r * ROWB + span);
            uint2 alo = pa[0], ahi = pa[1];
            uint2 slo = ps[0], shi = ps[1];
            v0 += alo.x - slo.x;
            v1 += alo.y - slo.y;
            v2 += ahi.x - shi.x;
            v3 += ahi.y - shi.y;
        }
    }
}

extern "C" void kernel_launch(void* const* d_in, const int* in_sizes, int n_in,
                              void* d_out, int out_size) {
    const float* x = (const float*)d_in[0];
    float* out = (float*)d_out;
    const int H = 1024, W = 1024;
    const int planes = out_size / (H * W);   // B*C = 48
    dim3 grid(W / TILE_W, H / TILE_H, planes);
    backedge_kernel<<<grid, NTHREADS>>>(x, out, H, W);
}

// round 6
// speedup vs baseline: 1.2513x; 1.2513x over previous
#include <cuda_runtime.h>

// BackEdgeConv2d fused: out = x * !(5 <= boxcount7x7(x >= 128/255, reflect) <= 19)
// x: [16,3,1024,1024] fp32. 3-phase, high-occupancy; rolling vertical sums in
// phase 2; SIMD prefix-sum horizontal + PTX-prmt sign-replicate mask in phase 3.

#define TILE_W 128
#define TILE_H 64
#define KPAD 3
#define PH (TILE_H + 2*KPAD)        // 70 padded rows
#define WPR 34                      // 136 cond bytes/row: byte j <-> global col c0-4+j
#define ROWB 136                    // row stride in bytes
#define U2PR 17                     // uint2 per row
#define NTHREADS 256

// PTX prmt: guarantees default-mode semantics incl. selector-bit-3 MSB-replicate.
__device__ __forceinline__ unsigned prmt(unsigned a, unsigned b, unsigned s) {
    unsigned r;
    asm("prmt.b32 %0, %1, %2, %3;" : "=r"(r) : "r"(a), "r"(b), "r"(s));
    return r;
}

__global__ __launch_bounds__(NTHREADS, 8)
void backedge_kernel(const float* __restrict__ x, float* __restrict__ out,
                     int H, int W) {
    __shared__ __align__(16) unsigned int scond[PH * WPR];      // 9520 B
    __shared__ __align__(16) unsigned int svsum[TILE_H * WPR];  // 8704 B

    const int tid = threadIdx.x;
    const int c0 = blockIdx.x * TILE_W;
    const int r0 = blockIdx.y * TILE_H;
    const long long plane = (long long)blockIdx.z * H * W;
    const float* xp = x + plane;
    float* op = out + plane;
    const float T = 128.0f / 255.0f;

    // ---- Phase 1: padded binary cond map, one uint32 word (4 px) per iter
    #pragma unroll 1
    for (int wi = tid; wi < PH * WPR; wi += NTHREADS) {
        int pr = wi / WPR;                    // const divisor -> mul.hi
        int w  = wi - pr * WPR;
        int gr = r0 + pr - KPAD;
        int gc = c0 + (w << 2) - 4;
        float4 v;
        if ((unsigned)gr < (unsigned)H && (unsigned)gc <= (unsigned)(W - 4)) {
            v = *(const float4*)(xp + gr * W + gc);          // aligned, coalesced
        } else {
            int rr = gr < 0 ? -gr : (gr >= H ? 2 * H - 2 - gr : gr);
            const float* rowp = xp + rr * W;
            int g0 = gc, g1 = gc + 1, g2 = gc + 2, g3 = gc + 3;
            g0 = g0 < 0 ? -g0 : (g0 >= W ? 2 * W - 2 - g0 : g0);
            g1 = g1 < 0 ? -g1 : (g1 >= W ? 2 * W - 2 - g1 : g1);
            g2 = g2 < 0 ? -g2 : (g2 >= W ? 2 * W - 2 - g2 : g2);
            g3 = g3 < 0 ? -g3 : (g3 >= W ? 2 * W - 2 - g3 : g3);
            v.x = rowp[g0]; v.y = rowp[g1]; v.z = rowp[g2]; v.w = rowp[g3];
        }
        unsigned int b0 = (v.x >= T) ? 1u : 0u;
        unsigned int b1 = (v.y >= T) ? (1u << 8) : 0u;
        unsigned int b2 = (v.z >= T) ? (1u << 16) : 0u;
        unsigned int b3 = (v.w >= T) ? (1u << 24) : 0u;
        scond[wi] = (b0 | b1) | (b2 | b3);
    }
    __syncthreads();

    // ---- Phase 2: vertical 7-sum, rolling over 4-row bands, uint2 byte-SIMD.
    //      Task = (band of 4 rows, uint2 column): 16 * 17 = 272 tasks.
    {
        const uint2* c2 = (const uint2*)scond;
        uint2* v2 = (uint2*)svsum;
        #pragma unroll 1
        for (int t = tid; t < (TILE_H / 4) * U2PR; t += NTHREADS) {
            int band = t / U2PR;              // const divisor
            int col  = t - band * U2PR;
            int rb = band << 2;
            const uint2* base = c2 + col;
            uint2 s = make_uint2(0u, 0u);
            #pragma unroll
            for (int k = 0; k < 7; k++) {
                uint2 a = base[(rb + k) * U2PR];
                s.x += a.x; s.y += a.y;
            }
            v2[rb * U2PR + col] = s;
            #pragma unroll
            for (int j = 1; j < 4; j++) {
                uint2 add = base[(rb + 6 + j) * U2PR];
                uint2 sub = base[(rb + j - 1) * U2PR];
                s.x += add.x - sub.x;        // byte-SIMD safe (counts <= 7)
                s.y += add.y - sub.y;
                v2[(rb + j) * U2PR + col] = s;
            }
        }
    }
    __syncthreads();

    // ---- Phase 3: 8 px/thread/row via SIMD prefix sums; prmt sign-replicate mask.
    const int tx = tid & 15;          // -> output px 8tx .. 8tx+7
    const int ty = tid >> 4;          // 16 rows per pass
    const int span = tx << 3;         // byte offset in row (8B aligned)
    const unsigned char* vsb = (const unsigned char*)svsum;

    #pragma unroll
    for (int rblk = 0; rblk < TILE_H; rblk += 16) {
        const int r = rblk + ty;
        const uint2* vs = (const uint2*)(vsb + r * ROWB + span);
        uint2 lo = vs[0], hi = vs[1];

        // byte prefix sums P[0..15] across the 16-byte span (max 112 < 256)
        unsigned p0 = lo.x * 0x01010101u;
        unsigned p1 = lo.y * 0x01010101u + prmt(p0, 0, 0x3333);
        unsigned p2 = hi.x * 0x01010101u + prmt(p1, 0, 0x3333);
        unsigned p3 = hi.y * 0x01010101u + prmt(p2, 0, 0x3333);
        // h_i = P[i+7] - P[i]  (window bytes i+1..i+7), packed 4/word
        unsigned hA = __vsub4(prmt(p1, p2, 0x6543), p0);   // px 0..3
        unsigned hB = __vsub4(prmt(p2, p3, 0x6543), p1);   // px 4..7

        // band 5..19 per byte -> MSB flag (h <= 49, no cross-byte carry)
        unsigned mA = (hA + 0x7B7B7B7Bu) & ~(hA + 0x6C6C6C6Cu) & 0x80808080u;
        unsigned mB = (hB + 0x7B7B7B7Bu) & ~(hB + 0x6C6C6C6Cu) & 0x80808080u;

        const float4* gx = (const float4*)(xp + (r0 + r) * W + c0 + span);
        float4 xa = gx[0], xb = gx[1];

        float4 oa, ob;
        oa.x = __uint_as_float(__float_as_uint(xa.x) & ~prmt(mA, 0, 0x8888));
        oa.y = __uint_as_float(__float_as_uint(xa.y) & ~prmt(mA, 0, 0x9999));
        oa.z = __uint_as_float(__float_as_uint(xa.z) & ~prmt(mA, 0, 0xAAAA));
        oa.w = __uint_as_float(__float_as_uint(xa.w) & ~prmt(mA, 0, 0xBBBB));
        ob.x = __uint_as_float(__float_as_uint(xb.x) & ~prmt(mB, 0, 0x8888));
        ob.y = __uint_as_float(__float_as_uint(xb.y) & ~prmt(mB, 0, 0x9999));
        ob.z = __uint_as_float(__float_as_uint(xb.z) & ~prmt(mB, 0, 0xAAAA));
        ob.w = __uint_as_float(__float_as_uint(xb.w) & ~prmt(mB, 0, 0xBBBB));

        float4* go = (float4*)(op + (r0 + r) * W + c0 + span);
        __stcs(go,     oa);
        __stcs(go + 1, ob);
    }
}

extern "C" void kernel_launch(void* const* d_in, const int* in_sizes, int n_in,
                              void* d_out, int out_size) {
    const float* x = (const float*)d_in[0];
    float* out = (float*)d_out;
    const int H = 1024, W = 1024;
    const int planes = out_size / (H * W);   // B*C = 48
    dim3 grid(W / TILE_W, H / TILE_H, planes);
    backedge_kernel<<<grid, NTHREADS>>>(x, out, H, W);
}